// round 11
// baseline (speedup 1.0000x reference)
#include <cuda_runtime.h>
#include <cuda_fp16.h>
#include <math.h>
#include <stdint.h>

#define BSZ 4096
#define DIM 1024
#define EPSF 1e-6f
#define INF_BITS 0x7f800000u

#define TM 128            // CTA tile M
#define TN 128            // CTA tile N
#define TK 64             // K halves per stage (128 B per row)
#define NSTAGE (DIM / TK) // 16 iterations
#define NBUF 3
#define THREADS 256       // 8 warps, 4x2 grid, warp tile 32x64
#define TOTAL_CTAS ((BSZ / TN) * (BSZ / TM) * 2)   // 2048

#define LD 72                        // padded halves per smem row (144 B)
#define A_ST (TM * LD)               // 9216 halves
#define B_ST (TN * LD)               // 9216 halves
#define STAGE_HALVES (A_ST + B_ST)   // 18432
#define SMEM_BYTES (NBUF * STAGE_HALVES * 2)  // 110592 -> 2 CTAs/SM

// ---------------- scratch ----------------
__device__ float g_sa1[BSZ], g_sa2[BSZ];
__device__ float g_sp1[BSZ], g_sp2[BSZ];
__device__ float g_sn1[BSZ], g_sn2[BSZ];
__device__ float g_dap[BSZ], g_danr[BSZ];
__device__ unsigned g_hardn[BSZ], g_hardp[BSZ];   // squared-distance bits
__device__ unsigned g_done;
__device__ __half g_Ah[BSZ * DIM];
__device__ __half g_Ph[BSZ * DIM];
__device__ __half g_Nh[BSZ * DIM];

// ---------------- helpers ----------------
__device__ __forceinline__ uint32_t smem_u32(const void* p) {
    uint32_t a;
    asm("{ .reg .u64 t; cvta.to.shared.u64 t, %1; cvt.u32.u64 %0, t; }"
        : "=r"(a) : "l"(p));
    return a;
}
__device__ __forceinline__ void cp16(uint32_t dst, const void* src) {
    asm volatile("cp.async.cg.shared.global [%0], [%1], 16;"
                 :: "r"(dst), "l"(src) : "memory");
}
__device__ __forceinline__ void ldsm_x4(uint32_t& r0, uint32_t& r1,
                                        uint32_t& r2, uint32_t& r3, uint32_t addr) {
    asm volatile("ldmatrix.sync.aligned.m8n8.x4.shared.b16 {%0,%1,%2,%3}, [%4];"
                 : "=r"(r0), "=r"(r1), "=r"(r2), "=r"(r3) : "r"(addr));
}
__device__ __forceinline__ void mma_f16(float* c, const uint32_t* a, const uint32_t* b) {
    asm volatile(
        "mma.sync.aligned.m16n8k16.row.col.f32.f16.f16.f32 "
        "{%0,%1,%2,%3}, {%4,%5,%6,%7}, {%8,%9}, {%0,%1,%2,%3};"
        : "+f"(c[0]), "+f"(c[1]), "+f"(c[2]), "+f"(c[3])
        : "r"(a[0]), "r"(a[1]), "r"(a[2]), "r"(a[3]), "r"(b[0]), "r"(b[1]));
}

// -------- per-row stats + fp16 conversion + aggregation init (fused) --------
__global__ __launch_bounds__(256) void rowstats_kernel(
    const float* __restrict__ A, const float* __restrict__ P,
    const float* __restrict__ N)
{
    const int row = blockIdx.x;
    const int tid = threadIdx.x;
    const float4* A4 = (const float4*)(A + (long)row * DIM);
    const float4* P4 = (const float4*)(P + (long)row * DIM);
    const float4* N4 = (const float4*)(N + (long)row * DIM);

    // streaming loads: fp32 inputs are read exactly once
    float4 a = __ldcs(A4 + tid), p = __ldcs(P4 + tid), n = __ldcs(N4 + tid);

    {
        __half2* Ah2 = (__half2*)(g_Ah + (long)row * DIM) + tid * 2;
        __half2* Ph2 = (__half2*)(g_Ph + (long)row * DIM) + tid * 2;
        __half2* Nh2 = (__half2*)(g_Nh + (long)row * DIM) + tid * 2;
        Ah2[0] = __floats2half2_rn(a.x, a.y);
        Ah2[1] = __floats2half2_rn(a.z, a.w);
        Ph2[0] = __floats2half2_rn(p.x, p.y);
        Ph2[1] = __floats2half2_rn(p.z, p.w);
        Nh2[0] = __floats2half2_rn(n.x, n.y);
        Nh2[1] = __floats2half2_rn(n.z, n.w);
    }
    if (tid == 0) {
        g_hardn[row] = 0u; g_hardp[row] = INF_BITS;
        if (row == 0) g_done = 0u;
    }

    float sa1 = a.x + a.y + a.z + a.w;
    float sa2 = a.x*a.x + a.y*a.y + a.z*a.z + a.w*a.w;
    float sp1 = p.x + p.y + p.z + p.w;
    float sp2 = p.x*p.x + p.y*p.y + p.z*p.z + p.w*p.w;
    float sn1 = n.x + n.y + n.z + n.w;
    float sn2 = n.x*n.x + n.y*n.y + n.z*n.z + n.w*n.w;

    float dx0 = a.x - p.x + EPSF, dx1 = a.y - p.y + EPSF,
          dx2 = a.z - p.z + EPSF, dx3 = a.w - p.w + EPSF;
    float dap = dx0*dx0 + dx1*dx1 + dx2*dx2 + dx3*dx3;
    float dy0 = a.x - n.x + EPSF, dy1 = a.y - n.y + EPSF,
          dy2 = a.z - n.z + EPSF, dy3 = a.w - n.w + EPSF;
    float dan = dy0*dy0 + dy1*dy1 + dy2*dy2 + dy3*dy3;

    #pragma unroll
    for (int off = 16; off; off >>= 1) {
        sa1 += __shfl_down_sync(0xffffffffu, sa1, off);
        sa2 += __shfl_down_sync(0xffffffffu, sa2, off);
        sp1 += __shfl_down_sync(0xffffffffu, sp1, off);
        sp2 += __shfl_down_sync(0xffffffffu, sp2, off);
        sn1 += __shfl_down_sync(0xffffffffu, sn1, off);
        sn2 += __shfl_down_sync(0xffffffffu, sn2, off);
        dap += __shfl_down_sync(0xffffffffu, dap, off);
        dan += __shfl_down_sync(0xffffffffu, dan, off);
    }

    __shared__ float sm[8][8];
    const int wid = tid >> 5, lane = tid & 31;
    if (lane == 0) {
        sm[0][wid] = sa1; sm[1][wid] = sa2; sm[2][wid] = sp1; sm[3][wid] = sp2;
        sm[4][wid] = sn1; sm[5][wid] = sn2; sm[6][wid] = dap; sm[7][wid] = dan;
    }
    __syncthreads();
    if (tid == 0) {
        float r[8];
        #pragma unroll
        for (int q = 0; q < 8; q++) {
            float s = 0.f;
            #pragma unroll
            for (int w = 0; w < 8; w++) s += sm[q][w];
            r[q] = s;
        }
        g_sa1[row] = r[0]; g_sa2[row] = r[1];
        g_sp1[row] = r[2]; g_sp2[row] = r[3];
        g_sn1[row] = r[4]; g_sn2[row] = r[5];
        g_dap[row]  = sqrtf(r[6]);
        g_danr[row] = sqrtf(r[7]);
    }
}

// ------- fused fp16 GEMM (8 warps, 32x64 warp tile, 3-stage pipe) -----------
// blockIdx.z == 0: B = negatives, mask sq < dap^2, max  -> g_hardn
// blockIdx.z == 1: B = positives, mask sq > danr^2, min -> g_hardp
// Last CTA to finish runs the finalize reduction in-place.
__global__ __launch_bounds__(THREADS, 2) void gemm_mma_kernel(float* __restrict__ out)
{
    extern __shared__ __half smem[];
    __shared__ unsigned rowRed[TM];
    __shared__ unsigned lastFlag;

    const int mode = blockIdx.z;
    const __half* Ah = g_Ah;
    const __half* Bh = (mode == 0) ? g_Nh : g_Ph;

    const int tid  = threadIdx.x;
    const int lane = tid & 31;
    const int wid  = tid >> 5;       // 0..7
    const int warpM = wid & 3;       // 4 m-blocks of 32
    const int warpN = wid >> 2;      // 2 n-blocks of 64
    const int m0 = blockIdx.y * TM;
    const int n0 = blockIdx.x * TN;

    // ---- gmem load mapping: 16B chunks (8 halves) of 128B k-slices ----
    const int chunk = tid & 7;       // 0..7
    const int rw    = tid >> 3;      // 0..31

    const __half* Ag = Ah + (long)(m0 + rw) * DIM + chunk * 8;
    const __half* Bg = Bh + (long)(n0 + rw) * DIM + chunk * 8;

    const uint32_t smem_base = smem_u32(smem);
    const uint32_t stWr = ((uint32_t)(rw * LD + chunk * 8)) * 2u;

    // ---- ldmatrix lane addressing (byte offsets within a stage) ----
    const int lane7 = lane & 7;
    const int rowA = warpM * 32 + lane7 + ((lane >> 3) & 1) * 8;
    const int colA = (lane >> 4) * 8;
    const uint32_t aOff = (uint32_t)(rowA * LD + colA) * 2u;
    const int rowB = warpN * 64 + lane7 + ((lane >> 4) & 1) * 8;
    const int colB = ((lane >> 3) & 1) * 8;
    const uint32_t bOff = (uint32_t)(A_ST + rowB * LD + colB) * 2u;

    float acc[2][8][4];
    #pragma unroll
    for (int mt = 0; mt < 2; mt++)
        #pragma unroll
        for (int nt = 0; nt < 8; nt++)
            #pragma unroll
            for (int q = 0; q < 4; q++) acc[mt][nt][q] = 0.f;

    // ---- prologue: stages 0 and 1 as full bursts ----
    #pragma unroll
    for (int s = 0; s < 2; s++) {
        const uint32_t sa = smem_base + (uint32_t)(s * STAGE_HALVES) * 2u + stWr;
        const int k0 = s * TK;
        #pragma unroll
        for (int r = 0; r < TM; r += 32)
            cp16(sa + (uint32_t)(r * LD) * 2u, Ag + (long)r * DIM + k0);
        #pragma unroll
        for (int r = 0; r < TN; r += 32)
            cp16(sa + (uint32_t)(A_ST + r * LD) * 2u, Bg + (long)r * DIM + k0);
        asm volatile("cp.async.commit_group;" ::: "memory");
    }

    const int r = lane >> 2, c = lane & 3;

    // ---- fully unrolled mainloop; next-stage loads spread across kk ----
    #pragma unroll
    for (int i = 0; i < NSTAGE; i++) {
        if (i >= NSTAGE - 1) asm volatile("cp.async.wait_group 0;" ::: "memory");
        else                 asm volatile("cp.async.wait_group 1;" ::: "memory");
        __syncthreads();

        const int buf  = i % NBUF;
        const int lbuf = (i + 2) % NBUF;
        const bool doLoad = (i + 2 < NSTAGE);
        const int k0n = (i + 2) * TK;
        const uint32_t stage = smem_base + (uint32_t)(buf * STAGE_HALVES) * 2u;
        const uint32_t lst   = smem_base + (uint32_t)(lbuf * STAGE_HALVES) * 2u + stWr;
        const uint32_t aBase = stage + aOff;
        const uint32_t bBase = stage + bOff;

        #pragma unroll
        for (int kk = 0; kk < 4; kk++) {
            const uint32_t kb = (uint32_t)kk * 32u;
            uint32_t afr[2][4];
            ldsm_x4(afr[0][0], afr[0][1], afr[0][2], afr[0][3], aBase + kb);
            ldsm_x4(afr[1][0], afr[1][1], afr[1][2], afr[1][3],
                    aBase + kb + 16u * LD * 2u);
            uint32_t bfr[8][2];
            #pragma unroll
            for (int ntp = 0; ntp < 4; ntp++)
                ldsm_x4(bfr[2*ntp][0], bfr[2*ntp][1],
                        bfr[2*ntp+1][0], bfr[2*ntp+1][1],
                        bBase + kb + (uint32_t)(ntp * 16 * LD) * 2u);

            if (doLoad) {
                if (kk < 2) {
                    const int r0 = kk * 64;
                    cp16(lst + (uint32_t)(r0 * LD) * 2u,
                         Ag + (long)r0 * DIM + k0n);
                    cp16(lst + (uint32_t)((r0 + 32) * LD) * 2u,
                         Ag + (long)(r0 + 32) * DIM + k0n);
                } else {
                    const int r0 = (kk - 2) * 64;
                    cp16(lst + (uint32_t)(A_ST + r0 * LD) * 2u,
                         Bg + (long)r0 * DIM + k0n);
                    cp16(lst + (uint32_t)(A_ST + (r0 + 32) * LD) * 2u,
                         Bg + (long)(r0 + 32) * DIM + k0n);
                }
            }

            #pragma unroll
            for (int mt = 0; mt < 2; mt++)
                #pragma unroll
                for (int nt = 0; nt < 8; nt++)
                    mma_f16(acc[mt][nt], afr[mt], bfr[nt]);
        }
        if (doLoad) asm volatile("cp.async.commit_group;" ::: "memory");
    }

    // ---- epilogue (squared domain) ----
    const float* colSq  = (mode == 0) ? g_sn2 : g_sp2;
    const float* colSum = (mode == 0) ? g_sn1 : g_sp1;
    const float* thr    = (mode == 0) ? g_dap : g_danr;
    unsigned* outAgg    = (mode == 0) ? g_hardn : g_hardp;

    const float inf = __uint_as_float(INF_BITS);
    const float deps2 = (float)DIM * EPSF * EPSF;

    float t2[2][2], rK[2][2], best[2][2];
    #pragma unroll
    for (int mt = 0; mt < 2; mt++)
        #pragma unroll
        for (int h = 0; h < 2; h++) {
            const int row = m0 + warpM * 32 + mt * 16 + r + h * 8;
            const float t = thr[row];
            t2[mt][h] = t * t;
            rK[mt][h] = g_sa2[row] + 2.f * EPSF * g_sa1[row] + deps2;
            best[mt][h] = (mode == 0) ? 0.f : inf;
        }

    float cK[8][2];
    #pragma unroll
    for (int nt = 0; nt < 8; nt++)
        #pragma unroll
        for (int jj = 0; jj < 2; jj++) {
            const int col = n0 + warpN * 64 + nt * 8 + 2 * c + jj;
            cK[nt][jj] = colSq[col] - 2.f * EPSF * colSum[col];
        }

    if (mode == 0) {
        #pragma unroll
        for (int mt = 0; mt < 2; mt++)
            #pragma unroll
            for (int nt = 0; nt < 8; nt++)
                #pragma unroll
                for (int h = 0; h < 2; h++)
                    #pragma unroll
                    for (int jj = 0; jj < 2; jj++) {
                        float sq = fmaf(-2.f, acc[mt][nt][h * 2 + jj],
                                        rK[mt][h] + cK[nt][jj]);
                        sq = fmaxf(sq, 0.f);
                        if (sq < t2[mt][h]) best[mt][h] = fmaxf(best[mt][h], sq);
                    }
    } else {
        #pragma unroll
        for (int mt = 0; mt < 2; mt++)
            #pragma unroll
            for (int nt = 0; nt < 8; nt++)
                #pragma unroll
                for (int h = 0; h < 2; h++)
                    #pragma unroll
                    for (int jj = 0; jj < 2; jj++) {
                        float sq = fmaf(-2.f, acc[mt][nt][h * 2 + jj],
                                        rK[mt][h] + cK[nt][jj]);
                        sq = fmaxf(sq, 0.f);
                        if (sq > t2[mt][h]) best[mt][h] = fminf(best[mt][h], sq);
                    }
    }

    #pragma unroll
    for (int off = 1; off <= 2; off <<= 1)
        #pragma unroll
        for (int mt = 0; mt < 2; mt++)
            #pragma unroll
            for (int h = 0; h < 2; h++) {
                const float o = __shfl_xor_sync(0xffffffffu, best[mt][h], off);
                best[mt][h] = (mode == 0) ? fmaxf(best[mt][h], o)
                                          : fminf(best[mt][h], o);
            }

    if (tid < TM) rowRed[tid] = (mode == 0) ? 0u : INF_BITS;
    __syncthreads();

    if ((lane & 3) == 0) {
        #pragma unroll
        for (int mt = 0; mt < 2; mt++)
            #pragma unroll
            for (int h = 0; h < 2; h++) {
                const int lr = warpM * 32 + mt * 16 + r + h * 8;
                if (mode == 0) {
                    if (best[mt][h] > 0.f)
                        atomicMax(&rowRed[lr], __float_as_uint(best[mt][h]));
                } else {
                    if (best[mt][h] < inf)
                        atomicMin(&rowRed[lr], __float_as_uint(best[mt][h]));
                }
            }
    }
    __syncthreads();

    if (tid < TM) {
        const unsigned v = rowRed[tid];
        if (mode == 0) { if (v != 0u)       atomicMax(&outAgg[m0 + tid], v); }
        else           { if (v != INF_BITS) atomicMin(&outAgg[m0 + tid], v); }
    }

    // ---- fused finalize: last CTA to finish runs the reduction ----
    __threadfence();
    __syncthreads();
    if (tid == 0) {
        const unsigned t = atomicAdd(&g_done, 1u);
        lastFlag = (t == TOTAL_CTAS - 1) ? 1u : 0u;
    }
    __syncthreads();
    if (lastFlag) {
        __threadfence();               // acquire: see all CTAs' atomics
        float* fsm = (float*)smem;     // tiles are dead; reuse dynamic smem

        float sn = 0.f, sp = 0.f;
        for (int i = tid; i < BSZ; i += THREADS) {
            sn += sqrtf(__uint_as_float(__ldcg(&g_hardn[i])));
            const unsigned hp = __ldcg(&g_hardp[i]);
            if (hp != INF_BITS) sp += sqrtf(__uint_as_float(hp));
        }
        fsm[tid] = sn; fsm[THREADS + tid] = sp;
        __syncthreads();
        for (int s = THREADS / 2; s; s >>= 1) {
            if (tid < s) {
                fsm[tid] += fsm[tid + s];
                fsm[THREADS + tid] += fsm[THREADS + tid + s];
            }
            __syncthreads();
        }
        const float bias = -0.5f * (fsm[THREADS] / (float)BSZ)
                           - 0.5f * (fsm[0] / (float)BSZ) + 1.0f;
        __syncthreads();

        float ls = 0.f;
        for (int i = tid; i < BSZ; i += THREADS)
            ls += fmaxf(g_dap[i] + bias, 0.f);
        fsm[tid] = ls;
        __syncthreads();
        for (int s = THREADS / 2; s; s >>= 1) {
            if (tid < s) fsm[tid] += fsm[tid + s];
            __syncthreads();
        }
        if (tid == 0) {
            out[0] = fsm[0] / (float)BSZ;
            g_done = 0u;               // reset for next graph replay
        }
    }
}

// ---------------- launch ----------------
extern "C" void kernel_launch(void* const* d_in, const int* in_sizes, int n_in,
                              void* d_out, int out_size)
{
    const float* A = (const float*)d_in[0];
    const float* P = (const float*)d_in[1];
    const float* N = (const float*)d_in[2];
    float* out = (float*)d_out;

    cudaFuncSetAttribute(gemm_mma_kernel,
                         cudaFuncAttributeMaxDynamicSharedMemorySize, SMEM_BYTES);

    rowstats_kernel<<<BSZ, 256>>>(A, P, N);

    dim3 grid(BSZ / TN, BSZ / TM, 2);   // (32, 32, 2)
    gemm_mma_kernel<<<grid, THREADS, SMEM_BYTES>>>(out);
}

// round 12
// speedup vs baseline: 1.0887x; 1.0887x over previous
#include <cuda_runtime.h>
#include <cuda_fp16.h>
#include <math.h>
#include <stdint.h>

#define BSZ 4096
#define DIM 1024
#define EPSF 1e-6f
#define INF_BITS 0x7f800000u

#define TM 128            // CTA tile M
#define TN 128            // CTA tile N
#define TK 64             // K halves per stage (128 B per row)
#define NSTAGE (DIM / TK) // 16 iterations
#define NBUF 3
#define THREADS 256       // 8 warps, 4x2 grid, warp tile 32x64

#define LD 72                        // padded halves per smem row (144 B)
#define A_ST (TM * LD)               // 9216 halves
#define B_ST (TN * LD)               // 9216 halves
#define STAGE_HALVES (A_ST + B_ST)   // 18432
#define SMEM_BYTES (NBUF * STAGE_HALVES * 2)  // 110592 -> 2 CTAs/SM

// ---------------- scratch ----------------
__device__ float g_rk[BSZ];                       // ||a||^2 + 2e*sum(a) + D*e^2
__device__ float g_ckn[BSZ], g_ckp[BSZ];          // ||b||^2 - 2e*sum(b)
__device__ float g_dap[BSZ], g_danr[BSZ];
__device__ unsigned g_hardn[BSZ], g_hardp[BSZ];   // squared-distance bits
__device__ __half g_Ah[BSZ * DIM];
__device__ __half g_Ph[BSZ * DIM];
__device__ __half g_Nh[BSZ * DIM];

// ---------------- helpers ----------------
__device__ __forceinline__ uint32_t smem_u32(const void* p) {
    uint32_t a;
    asm("{ .reg .u64 t; cvta.to.shared.u64 t, %1; cvt.u32.u64 %0, t; }"
        : "=r"(a) : "l"(p));
    return a;
}
__device__ __forceinline__ void cp16(uint32_t dst, const void* src) {
    asm volatile("cp.async.cg.shared.global [%0], [%1], 16;"
                 :: "r"(dst), "l"(src) : "memory");
}
__device__ __forceinline__ void ldsm_x4(uint32_t& r0, uint32_t& r1,
                                        uint32_t& r2, uint32_t& r3, uint32_t addr) {
    asm volatile("ldmatrix.sync.aligned.m8n8.x4.shared.b16 {%0,%1,%2,%3}, [%4];"
                 : "=r"(r0), "=r"(r1), "=r"(r2), "=r"(r3) : "r"(addr));
}
__device__ __forceinline__ void mma_f16(float* c, const uint32_t* a, const uint32_t* b) {
    asm volatile(
        "mma.sync.aligned.m16n8k16.row.col.f32.f16.f16.f32 "
        "{%0,%1,%2,%3}, {%4,%5,%6,%7}, {%8,%9}, {%0,%1,%2,%3};"
        : "+f"(c[0]), "+f"(c[1]), "+f"(c[2]), "+f"(c[3])
        : "r"(a[0]), "r"(a[1]), "r"(a[2]), "r"(a[3]), "r"(b[0]), "r"(b[1]));
}

// ---- per-row stats (2 rows/block, MLP=6) + fp16 convert + init (fused) ----
__global__ __launch_bounds__(256) void rowstats_kernel(
    const float* __restrict__ A, const float* __restrict__ P,
    const float* __restrict__ N)
{
    const int tid  = threadIdx.x;
    const int half = tid >> 7;                 // 0..1: which row of the pair
    const int j    = tid & 127;                // 0..127: float4 index base
    const int row  = blockIdx.x * 2 + half;

    const float4* A4 = (const float4*)(A + (long)row * DIM);
    const float4* P4 = (const float4*)(P + (long)row * DIM);
    const float4* N4 = (const float4*)(N + (long)row * DIM);

    // 6 independent streaming loads in flight per thread
    float4 a0 = __ldcs(A4 + j), a1 = __ldcs(A4 + j + 128);
    float4 p0 = __ldcs(P4 + j), p1 = __ldcs(P4 + j + 128);
    float4 n0 = __ldcs(N4 + j), n1 = __ldcs(N4 + j + 128);

    // fp16 copies (RN)
    {
        __half2* Ah2 = (__half2*)(g_Ah + (long)row * DIM);
        __half2* Ph2 = (__half2*)(g_Ph + (long)row * DIM);
        __half2* Nh2 = (__half2*)(g_Nh + (long)row * DIM);
        Ah2[j*2]   = __floats2half2_rn(a0.x, a0.y);
        Ah2[j*2+1] = __floats2half2_rn(a0.z, a0.w);
        Ah2[(j+128)*2]   = __floats2half2_rn(a1.x, a1.y);
        Ah2[(j+128)*2+1] = __floats2half2_rn(a1.z, a1.w);
        Ph2[j*2]   = __floats2half2_rn(p0.x, p0.y);
        Ph2[j*2+1] = __floats2half2_rn(p0.z, p0.w);
        Ph2[(j+128)*2]   = __floats2half2_rn(p1.x, p1.y);
        Ph2[(j+128)*2+1] = __floats2half2_rn(p1.z, p1.w);
        Nh2[j*2]   = __floats2half2_rn(n0.x, n0.y);
        Nh2[j*2+1] = __floats2half2_rn(n0.z, n0.w);
        Nh2[(j+128)*2]   = __floats2half2_rn(n1.x, n1.y);
        Nh2[(j+128)*2+1] = __floats2half2_rn(n1.z, n1.w);
    }
    if (j == 0) { g_hardn[row] = 0u; g_hardp[row] = INF_BITS; }

    float sa1 = a0.x+a0.y+a0.z+a0.w + a1.x+a1.y+a1.z+a1.w;
    float sa2 = a0.x*a0.x+a0.y*a0.y+a0.z*a0.z+a0.w*a0.w
              + a1.x*a1.x+a1.y*a1.y+a1.z*a1.z+a1.w*a1.w;
    float sp1 = p0.x+p0.y+p0.z+p0.w + p1.x+p1.y+p1.z+p1.w;
    float sp2 = p0.x*p0.x+p0.y*p0.y+p0.z*p0.z+p0.w*p0.w
              + p1.x*p1.x+p1.y*p1.y+p1.z*p1.z+p1.w*p1.w;
    float sn1 = n0.x+n0.y+n0.z+n0.w + n1.x+n1.y+n1.z+n1.w;
    float sn2 = n0.x*n0.x+n0.y*n0.y+n0.z*n0.z+n0.w*n0.w
              + n1.x*n1.x+n1.y*n1.y+n1.z*n1.z+n1.w*n1.w;

    float dap, dan;
    {
        float d0 = a0.x-p0.x+EPSF, d1 = a0.y-p0.y+EPSF,
              d2 = a0.z-p0.z+EPSF, d3 = a0.w-p0.w+EPSF;
        float e0 = a1.x-p1.x+EPSF, e1 = a1.y-p1.y+EPSF,
              e2 = a1.z-p1.z+EPSF, e3 = a1.w-p1.w+EPSF;
        dap = d0*d0+d1*d1+d2*d2+d3*d3 + e0*e0+e1*e1+e2*e2+e3*e3;
        float f0 = a0.x-n0.x+EPSF, f1 = a0.y-n0.y+EPSF,
              f2 = a0.z-n0.z+EPSF, f3 = a0.w-n0.w+EPSF;
        float g0 = a1.x-n1.x+EPSF, g1 = a1.y-n1.y+EPSF,
              g2 = a1.z-n1.z+EPSF, g3 = a1.w-n1.w+EPSF;
        dan = f0*f0+f1*f1+f2*f2+f3*f3 + g0*g0+g1*g1+g2*g2+g3*g3;
    }

    #pragma unroll
    for (int off = 16; off; off >>= 1) {
        sa1 += __shfl_down_sync(0xffffffffu, sa1, off);
        sa2 += __shfl_down_sync(0xffffffffu, sa2, off);
        sp1 += __shfl_down_sync(0xffffffffu, sp1, off);
        sp2 += __shfl_down_sync(0xffffffffu, sp2, off);
        sn1 += __shfl_down_sync(0xffffffffu, sn1, off);
        sn2 += __shfl_down_sync(0xffffffffu, sn2, off);
        dap += __shfl_down_sync(0xffffffffu, dap, off);
        dan += __shfl_down_sync(0xffffffffu, dan, off);
    }

    __shared__ float sm[2][8][4];
    const int wlocal = (tid >> 5) & 3;      // warp index within the row group
    if ((tid & 31) == 0) {
        sm[half][0][wlocal] = sa1; sm[half][1][wlocal] = sa2;
        sm[half][2][wlocal] = sp1; sm[half][3][wlocal] = sp2;
        sm[half][4][wlocal] = sn1; sm[half][5][wlocal] = sn2;
        sm[half][6][wlocal] = dap; sm[half][7][wlocal] = dan;
    }
    __syncthreads();
    if (j == 0) {
        float r[8];
        #pragma unroll
        for (int q = 0; q < 8; q++)
            r[q] = sm[half][q][0] + sm[half][q][1] + sm[half][q][2] + sm[half][q][3];
        const float deps2 = (float)DIM * EPSF * EPSF;
        g_rk[row]  = r[1] + 2.f * EPSF * r[0] + deps2;
        g_ckp[row] = r[3] - 2.f * EPSF * r[2];
        g_ckn[row] = r[5] - 2.f * EPSF * r[4];
        g_dap[row]  = sqrtf(r[6]);
        g_danr[row] = sqrtf(r[7]);
    }
}

// ------- fused fp16 GEMM (8 warps, 32x64 warp tile, 3-stage pipe) -----------
// blockIdx.z == 0: B = negatives, mask sq < dap^2, max  -> g_hardn
// blockIdx.z == 1: B = positives, mask sq > danr^2, min -> g_hardp
__global__ __launch_bounds__(THREADS, 2) void gemm_mma_kernel()
{
    extern __shared__ __half smem[];
    __shared__ unsigned rowRed[TM];

    const int mode = blockIdx.z;
    const __half* Ah = g_Ah;
    const __half* Bh = (mode == 0) ? g_Nh : g_Ph;

    const int tid  = threadIdx.x;
    const int lane = tid & 31;
    const int wid  = tid >> 5;       // 0..7
    const int warpM = wid & 3;       // 4 m-blocks of 32
    const int warpN = wid >> 2;      // 2 n-blocks of 64
    const int m0 = blockIdx.y * TM;
    const int n0 = blockIdx.x * TN;

    // ---- gmem load mapping: 16B chunks (8 halves) of 128B k-slices ----
    const int chunk = tid & 7;       // 0..7
    const int rw    = tid >> 3;      // 0..31

    const __half* Ag = Ah + (long)(m0 + rw) * DIM + chunk * 8;
    const __half* Bg = Bh + (long)(n0 + rw) * DIM + chunk * 8;

    const uint32_t smem_base = smem_u32(smem);
    const uint32_t stWr = ((uint32_t)(rw * LD + chunk * 8)) * 2u;

    // ---- ldmatrix lane addressing (byte offsets within a stage) ----
    const int lane7 = lane & 7;
    const int rowA = warpM * 32 + lane7 + ((lane >> 3) & 1) * 8;
    const int colA = (lane >> 4) * 8;
    const uint32_t aOff = (uint32_t)(rowA * LD + colA) * 2u;
    const int rowB = warpN * 64 + lane7 + ((lane >> 4) & 1) * 8;
    const int colB = ((lane >> 3) & 1) * 8;
    const uint32_t bOff = (uint32_t)(A_ST + rowB * LD + colB) * 2u;

    float acc[2][8][4];
    #pragma unroll
    for (int mt = 0; mt < 2; mt++)
        #pragma unroll
        for (int nt = 0; nt < 8; nt++)
            #pragma unroll
            for (int q = 0; q < 4; q++) acc[mt][nt][q] = 0.f;

    // ---- prologue: stages 0 and 1 as full bursts ----
    #pragma unroll
    for (int s = 0; s < 2; s++) {
        const uint32_t sa = smem_base + (uint32_t)(s * STAGE_HALVES) * 2u + stWr;
        const int k0 = s * TK;
        #pragma unroll
        for (int r = 0; r < TM; r += 32)
            cp16(sa + (uint32_t)(r * LD) * 2u, Ag + (long)r * DIM + k0);
        #pragma unroll
        for (int r = 0; r < TN; r += 32)
            cp16(sa + (uint32_t)(A_ST + r * LD) * 2u, Bg + (long)r * DIM + k0);
        asm volatile("cp.async.commit_group;" ::: "memory");
    }

    const int r = lane >> 2, c = lane & 3;

    // ---- fully unrolled mainloop; next-stage loads spread across kk ----
    #pragma unroll
    for (int i = 0; i < NSTAGE; i++) {
        if (i >= NSTAGE - 1) asm volatile("cp.async.wait_group 0;" ::: "memory");
        else                 asm volatile("cp.async.wait_group 1;" ::: "memory");
        __syncthreads();

        const int buf  = i % NBUF;
        const int lbuf = (i + 2) % NBUF;
        const bool doLoad = (i + 2 < NSTAGE);
        const int k0n = (i + 2) * TK;
        const uint32_t stage = smem_base + (uint32_t)(buf * STAGE_HALVES) * 2u;
        const uint32_t lst   = smem_base + (uint32_t)(lbuf * STAGE_HALVES) * 2u + stWr;
        const uint32_t aBase = stage + aOff;
        const uint32_t bBase = stage + bOff;

        #pragma unroll
        for (int kk = 0; kk < 4; kk++) {
            const uint32_t kb = (uint32_t)kk * 32u;
            uint32_t afr[2][4];
            ldsm_x4(afr[0][0], afr[0][1], afr[0][2], afr[0][3], aBase + kb);
            ldsm_x4(afr[1][0], afr[1][1], afr[1][2], afr[1][3],
                    aBase + kb + 16u * LD * 2u);
            uint32_t bfr[8][2];
            #pragma unroll
            for (int ntp = 0; ntp < 4; ntp++)
                ldsm_x4(bfr[2*ntp][0], bfr[2*ntp][1],
                        bfr[2*ntp+1][0], bfr[2*ntp+1][1],
                        bBase + kb + (uint32_t)(ntp * 16 * LD) * 2u);

            if (doLoad) {
                if (kk < 2) {
                    const int r0 = kk * 64;
                    cp16(lst + (uint32_t)(r0 * LD) * 2u,
                         Ag + (long)r0 * DIM + k0n);
                    cp16(lst + (uint32_t)((r0 + 32) * LD) * 2u,
                         Ag + (long)(r0 + 32) * DIM + k0n);
                } else {
                    const int r0 = (kk - 2) * 64;
                    cp16(lst + (uint32_t)(A_ST + r0 * LD) * 2u,
                         Bg + (long)r0 * DIM + k0n);
                    cp16(lst + (uint32_t)(A_ST + (r0 + 32) * LD) * 2u,
                         Bg + (long)(r0 + 32) * DIM + k0n);
                }
            }

            #pragma unroll
            for (int mt = 0; mt < 2; mt++)
                #pragma unroll
                for (int nt = 0; nt < 8; nt++)
                    mma_f16(acc[mt][nt], afr[mt], bfr[nt]);
        }
        if (doLoad) asm volatile("cp.async.commit_group;" ::: "memory");
    }

    // ---- epilogue (squared domain; folded constants) ----
    const float* ckArr = (mode == 0) ? g_ckn : g_ckp;
    const float* thr   = (mode == 0) ? g_dap : g_danr;
    unsigned* outAgg   = (mode == 0) ? g_hardn : g_hardp;

    const float inf = __uint_as_float(INF_BITS);

    float t2[2][2], rK[2][2], best[2][2];
    #pragma unroll
    for (int mt = 0; mt < 2; mt++)
        #pragma unroll
        for (int h = 0; h < 2; h++) {
            const int row = m0 + warpM * 32 + mt * 16 + r + h * 8;
            const float t = thr[row];
            t2[mt][h] = t * t;
            rK[mt][h] = g_rk[row];
            best[mt][h] = (mode == 0) ? 0.f : inf;
        }

    float cK[8][2];
    #pragma unroll
    for (int nt = 0; nt < 8; nt++)
        #pragma unroll
        for (int jj = 0; jj < 2; jj++)
            cK[nt][jj] = ckArr[n0 + warpN * 64 + nt * 8 + 2 * c + jj];

    if (mode == 0) {
        #pragma unroll
        for (int mt = 0; mt < 2; mt++)
            #pragma unroll
            for (int nt = 0; nt < 8; nt++)
                #pragma unroll
                for (int h = 0; h < 2; h++)
                    #pragma unroll
                    for (int jj = 0; jj < 2; jj++) {
                        float sq = fmaf(-2.f, acc[mt][nt][h * 2 + jj],
                                        rK[mt][h] + cK[nt][jj]);
                        sq = fmaxf(sq, 0.f);
                        if (sq < t2[mt][h]) best[mt][h] = fmaxf(best[mt][h], sq);
                    }
    } else {
        #pragma unroll
        for (int mt = 0; mt < 2; mt++)
            #pragma unroll
            for (int nt = 0; nt < 8; nt++)
                #pragma unroll
                for (int h = 0; h < 2; h++)
                    #pragma unroll
                    for (int jj = 0; jj < 2; jj++) {
                        float sq = fmaf(-2.f, acc[mt][nt][h * 2 + jj],
                                        rK[mt][h] + cK[nt][jj]);
                        sq = fmaxf(sq, 0.f);
                        if (sq > t2[mt][h]) best[mt][h] = fminf(best[mt][h], sq);
                    }
    }

    #pragma unroll
    for (int off = 1; off <= 2; off <<= 1)
        #pragma unroll
        for (int mt = 0; mt < 2; mt++)
            #pragma unroll
            for (int h = 0; h < 2; h++) {
                const float o = __shfl_xor_sync(0xffffffffu, best[mt][h], off);
                best[mt][h] = (mode == 0) ? fmaxf(best[mt][h], o)
                                          : fminf(best[mt][h], o);
            }

    if (tid < TM) rowRed[tid] = (mode == 0) ? 0u : INF_BITS;
    __syncthreads();

    if ((lane & 3) == 0) {
        #pragma unroll
        for (int mt = 0; mt < 2; mt++)
            #pragma unroll
            for (int h = 0; h < 2; h++) {
                const int lr = warpM * 32 + mt * 16 + r + h * 8;
                if (mode == 0) {
                    if (best[mt][h] > 0.f)
                        atomicMax(&rowRed[lr], __float_as_uint(best[mt][h]));
                } else {
                    if (best[mt][h] < inf)
                        atomicMin(&rowRed[lr], __float_as_uint(best[mt][h]));
                }
            }
    }
    __syncthreads();

    if (tid < TM) {
        const unsigned v = rowRed[tid];
        if (mode == 0) { if (v != 0u)       atomicMax(&outAgg[m0 + tid], v); }
        else           { if (v != INF_BITS) atomicMin(&outAgg[m0 + tid], v); }
    }
}

// ---------- finalize: single-block (1024 thr) reduce + loss ----------
__global__ __launch_bounds__(1024) void finalize_kernel(float* __restrict__ out)
{
    __shared__ float s1[1024], s2[1024];
    __shared__ float dan_s, dpp_s;
    const int tid = threadIdx.x;

    float sn = 0.f, sp = 0.f;
    for (int i = tid; i < BSZ; i += 1024) {
        sn += sqrtf(__uint_as_float(g_hardn[i]));
        unsigned hp = g_hardp[i];
        if (hp != INF_BITS) sp += sqrtf(__uint_as_float(hp));
    }
    s1[tid] = sn; s2[tid] = sp;
    __syncthreads();
    for (int s = 512; s; s >>= 1) {
        if (tid < s) { s1[tid] += s1[tid + s]; s2[tid] += s2[tid + s]; }
        __syncthreads();
    }
    if (tid == 0) { dan_s = s1[0] / (float)BSZ; dpp_s = s2[0] / (float)BSZ; }
    __syncthreads();
    const float bias = -0.5f * dpp_s - 0.5f * dan_s + 1.0f;

    float ls = 0.f;
    for (int i = tid; i < BSZ; i += 1024)
        ls += fmaxf(g_dap[i] + bias, 0.f);
    s1[tid] = ls;
    __syncthreads();
    for (int s = 512; s; s >>= 1) {
        if (tid < s) s1[tid] += s1[tid + s];
        __syncthreads();
    }
    if (tid == 0) out[0] = s1[0] / (float)BSZ;
}

// ---------------- launch ----------------
extern "C" void kernel_launch(void* const* d_in, const int* in_sizes, int n_in,
                              void* d_out, int out_size)
{
    const float* A = (const float*)d_in[0];
    const float* P = (const float*)d_in[1];
    const float* N = (const float*)d_in[2];
    float* out = (float*)d_out;

    cudaFuncSetAttribute(gemm_mma_kernel,
                         cudaFuncAttributeMaxDynamicSharedMemorySize, SMEM_BYTES);

    rowstats_kernel<<<BSZ / 2, 256>>>(A, P, N);

    dim3 grid(BSZ / TN, BSZ / TM, 2);   // (32, 32, 2)
    gemm_mma_kernel<<<grid, THREADS, SMEM_BYTES>>>();

    finalize_kernel<<<1, 1024>>>(out);
}

// round 13
// speedup vs baseline: 1.1161x; 1.0252x over previous
#include <cuda_runtime.h>
#include <cuda_fp16.h>
#include <math.h>
#include <stdint.h>

#define BSZ 4096
#define DIM 1024
#define EPSF 1e-6f
#define INF_BITS 0x7f800000u

#define TM 128            // CTA tile M
#define TN 128            // CTA tile N
#define TK 64             // K halves per stage (128 B per row)
#define NSTAGE (DIM / TK) // 16 iterations
#define NBUF 3
#define THREADS 256       // 8 warps, 4x2 grid, warp tile 32x64

#define LD 72                        // padded halves per smem row (144 B)
#define A_ST (TM * LD)               // 9216 halves
#define B_ST (TN * LD)               // 9216 halves
#define STAGE_HALVES (A_ST + B_ST)   // 18432
#define SMEM_BYTES (NBUF * STAGE_HALVES * 2)  // 110592 -> 2 CTAs/SM

// ---------------- scratch ----------------
__device__ float g_rk[BSZ];                       // ||a||^2 + 2e*sum(a) + D*e^2
__device__ float g_ckn[BSZ], g_ckp[BSZ];          // ||b||^2 - 2e*sum(b)
__device__ float g_dap[BSZ], g_danr[BSZ];
__device__ unsigned g_hardn[BSZ], g_hardp[BSZ];   // squared-distance bits
__device__ __half g_Ah[BSZ * DIM];
__device__ __half g_Ph[BSZ * DIM];
__device__ __half g_Nh[BSZ * DIM];

// ---------------- helpers ----------------
__device__ __forceinline__ uint32_t smem_u32(const void* p) {
    uint32_t a;
    asm("{ .reg .u64 t; cvta.to.shared.u64 t, %1; cvt.u32.u64 %0, t; }"
        : "=r"(a) : "l"(p));
    return a;
}
__device__ __forceinline__ void cp16(uint32_t dst, const void* src) {
    asm volatile("cp.async.cg.shared.global [%0], [%1], 16;"
                 :: "r"(dst), "l"(src) : "memory");
}
__device__ __forceinline__ void ldsm_x4(uint32_t& r0, uint32_t& r1,
                                        uint32_t& r2, uint32_t& r3, uint32_t addr) {
    asm volatile("ldmatrix.sync.aligned.m8n8.x4.shared.b16 {%0,%1,%2,%3}, [%4];"
                 : "=r"(r0), "=r"(r1), "=r"(r2), "=r"(r3) : "r"(addr));
}
__device__ __forceinline__ void mma_f16(float* c, const uint32_t* a, const uint32_t* b) {
    asm volatile(
        "mma.sync.aligned.m16n8k16.row.col.f32.f16.f16.f32 "
        "{%0,%1,%2,%3}, {%4,%5,%6,%7}, {%8,%9}, {%0,%1,%2,%3};"
        : "+f"(c[0]), "+f"(c[1]), "+f"(c[2]), "+f"(c[3])
        : "r"(a[0]), "r"(a[1]), "r"(a[2]), "r"(a[3]), "r"(b[0]), "r"(b[1]));
}
// PDL controls
__device__ __forceinline__ void gdc_wait() {
    asm volatile("griddepcontrol.wait;" ::: "memory");
}
__device__ __forceinline__ void gdc_launch() {
    asm volatile("griddepcontrol.launch_dependents;" ::: "memory");
}

// ---- per-row stats (2 rows/block, MLP=6) + fp16 convert + init (fused) ----
__global__ __launch_bounds__(256) void rowstats_kernel(
    const float* __restrict__ A, const float* __restrict__ P,
    const float* __restrict__ N)
{
    const int tid  = threadIdx.x;
    const int half = tid >> 7;                 // 0..1: which row of the pair
    const int j    = tid & 127;                // 0..127: float4 index base
    const int row  = blockIdx.x * 2 + half;

    const float4* A4 = (const float4*)(A + (long)row * DIM);
    const float4* P4 = (const float4*)(P + (long)row * DIM);
    const float4* N4 = (const float4*)(N + (long)row * DIM);

    float4 a0 = __ldcs(A4 + j), a1 = __ldcs(A4 + j + 128);
    float4 p0 = __ldcs(P4 + j), p1 = __ldcs(P4 + j + 128);
    float4 n0 = __ldcs(N4 + j), n1 = __ldcs(N4 + j + 128);

    {
        __half2* Ah2 = (__half2*)(g_Ah + (long)row * DIM);
        __half2* Ph2 = (__half2*)(g_Ph + (long)row * DIM);
        __half2* Nh2 = (__half2*)(g_Nh + (long)row * DIM);
        Ah2[j*2]   = __floats2half2_rn(a0.x, a0.y);
        Ah2[j*2+1] = __floats2half2_rn(a0.z, a0.w);
        Ah2[(j+128)*2]   = __floats2half2_rn(a1.x, a1.y);
        Ah2[(j+128)*2+1] = __floats2half2_rn(a1.z, a1.w);
        Ph2[j*2]   = __floats2half2_rn(p0.x, p0.y);
        Ph2[j*2+1] = __floats2half2_rn(p0.z, p0.w);
        Ph2[(j+128)*2]   = __floats2half2_rn(p1.x, p1.y);
        Ph2[(j+128)*2+1] = __floats2half2_rn(p1.z, p1.w);
        Nh2[j*2]   = __floats2half2_rn(n0.x, n0.y);
        Nh2[j*2+1] = __floats2half2_rn(n0.z, n0.w);
        Nh2[(j+128)*2]   = __floats2half2_rn(n1.x, n1.y);
        Nh2[(j+128)*2+1] = __floats2half2_rn(n1.z, n1.w);
    }
    if (j == 0) { g_hardn[row] = 0u; g_hardp[row] = INF_BITS; }

    float sa1 = a0.x+a0.y+a0.z+a0.w + a1.x+a1.y+a1.z+a1.w;
    float sa2 = a0.x*a0.x+a0.y*a0.y+a0.z*a0.z+a0.w*a0.w
              + a1.x*a1.x+a1.y*a1.y+a1.z*a1.z+a1.w*a1.w;
    float sp1 = p0.x+p0.y+p0.z+p0.w + p1.x+p1.y+p1.z+p1.w;
    float sp2 = p0.x*p0.x+p0.y*p0.y+p0.z*p0.z+p0.w*p0.w
              + p1.x*p1.x+p1.y*p1.y+p1.z*p1.z+p1.w*p1.w;
    float sn1 = n0.x+n0.y+n0.z+n0.w + n1.x+n1.y+n1.z+n1.w;
    float sn2 = n0.x*n0.x+n0.y*n0.y+n0.z*n0.z+n0.w*n0.w
              + n1.x*n1.x+n1.y*n1.y+n1.z*n1.z+n1.w*n1.w;

    float dap, dan;
    {
        float d0 = a0.x-p0.x+EPSF, d1 = a0.y-p0.y+EPSF,
              d2 = a0.z-p0.z+EPSF, d3 = a0.w-p0.w+EPSF;
        float e0 = a1.x-p1.x+EPSF, e1 = a1.y-p1.y+EPSF,
              e2 = a1.z-p1.z+EPSF, e3 = a1.w-p1.w+EPSF;
        dap = d0*d0+d1*d1+d2*d2+d3*d3 + e0*e0+e1*e1+e2*e2+e3*e3;
        float f0 = a0.x-n0.x+EPSF, f1 = a0.y-n0.y+EPSF,
              f2 = a0.z-n0.z+EPSF, f3 = a0.w-n0.w+EPSF;
        float g0 = a1.x-n1.x+EPSF, g1 = a1.y-n1.y+EPSF,
              g2 = a1.z-n1.z+EPSF, g3 = a1.w-n1.w+EPSF;
        dan = f0*f0+f1*f1+f2*f2+f3*f3 + g0*g0+g1*g1+g2*g2+g3*g3;
    }

    #pragma unroll
    for (int off = 16; off; off >>= 1) {
        sa1 += __shfl_down_sync(0xffffffffu, sa1, off);
        sa2 += __shfl_down_sync(0xffffffffu, sa2, off);
        sp1 += __shfl_down_sync(0xffffffffu, sp1, off);
        sp2 += __shfl_down_sync(0xffffffffu, sp2, off);
        sn1 += __shfl_down_sync(0xffffffffu, sn1, off);
        sn2 += __shfl_down_sync(0xffffffffu, sn2, off);
        dap += __shfl_down_sync(0xffffffffu, dap, off);
        dan += __shfl_down_sync(0xffffffffu, dan, off);
    }

    __shared__ float sm[2][8][4];
    const int wlocal = (tid >> 5) & 3;
    if ((tid & 31) == 0) {
        sm[half][0][wlocal] = sa1; sm[half][1][wlocal] = sa2;
        sm[half][2][wlocal] = sp1; sm[half][3][wlocal] = sp2;
        sm[half][4][wlocal] = sn1; sm[half][5][wlocal] = sn2;
        sm[half][6][wlocal] = dap; sm[half][7][wlocal] = dan;
    }
    __syncthreads();
    if (j == 0) {
        float r[8];
        #pragma unroll
        for (int q = 0; q < 8; q++)
            r[q] = sm[half][q][0] + sm[half][q][1] + sm[half][q][2] + sm[half][q][3];
        const float deps2 = (float)DIM * EPSF * EPSF;
        g_rk[row]  = r[1] + 2.f * EPSF * r[0] + deps2;
        g_ckp[row] = r[3] - 2.f * EPSF * r[2];
        g_ckn[row] = r[5] - 2.f * EPSF * r[4];
        g_dap[row]  = sqrtf(r[6]);
        g_danr[row] = sqrtf(r[7]);
    }
    __syncthreads();
    gdc_launch();
}

// ------- fused fp16 GEMM (8 warps, 32x64 warp tile, 3-stage pipe) -----------
// blockIdx.z == 0: B = negatives, mask sq < dap^2, max  -> g_hardn
// blockIdx.z == 1: B = positives, mask sq > danr^2, min -> g_hardp
__global__ __launch_bounds__(THREADS, 2) void gemm_mma_kernel()
{
    extern __shared__ __half smem[];
    __shared__ unsigned rowRed[TM];

    const int mode = blockIdx.z;
    const __half* Ah = g_Ah;
    const __half* Bh = (mode == 0) ? g_Nh : g_Ph;

    const int tid  = threadIdx.x;
    const int lane = tid & 31;
    const int wid  = tid >> 5;       // 0..7
    const int warpM = wid & 3;       // 4 m-blocks of 32
    const int warpN = wid >> 2;      // 2 n-blocks of 64
    const int m0 = blockIdx.y * TM;
    const int n0 = blockIdx.x * TN;

    const int chunk = tid & 7;       // 0..7
    const int rw    = tid >> 3;      // 0..31

    const __half* Ag = Ah + (long)(m0 + rw) * DIM + chunk * 8;
    const __half* Bg = Bh + (long)(n0 + rw) * DIM + chunk * 8;

    const uint32_t smem_base = smem_u32(smem);
    const uint32_t stWr = ((uint32_t)(rw * LD + chunk * 8)) * 2u;

    const int lane7 = lane & 7;
    const int rowA = warpM * 32 + lane7 + ((lane >> 3) & 1) * 8;
    const int colA = (lane >> 4) * 8;
    const uint32_t aOff = (uint32_t)(rowA * LD + colA) * 2u;
    const int rowB = warpN * 64 + lane7 + ((lane >> 4) & 1) * 8;
    const int colB = ((lane >> 3) & 1) * 8;
    const uint32_t bOff = (uint32_t)(A_ST + rowB * LD + colB) * 2u;

    float acc[2][8][4];
    #pragma unroll
    for (int mt = 0; mt < 2; mt++)
        #pragma unroll
        for (int nt = 0; nt < 8; nt++)
            #pragma unroll
            for (int q = 0; q < 4; q++) acc[mt][nt][q] = 0.f;

    // wait for rowstats results before touching g_Ah/g_Nh/g_Ph
    gdc_wait();

    // ---- prologue: stages 0 and 1 as full bursts ----
    #pragma unroll
    for (int s = 0; s < 2; s++) {
        const uint32_t sa = smem_base + (uint32_t)(s * STAGE_HALVES) * 2u + stWr;
        const int k0 = s * TK;
        #pragma unroll
        for (int r = 0; r < TM; r += 32)
            cp16(sa + (uint32_t)(r * LD) * 2u, Ag + (long)r * DIM + k0);
        #pragma unroll
        for (int r = 0; r < TN; r += 32)
            cp16(sa + (uint32_t)(A_ST + r * LD) * 2u, Bg + (long)r * DIM + k0);
        asm volatile("cp.async.commit_group;" ::: "memory");
    }

    const int r = lane >> 2, c = lane & 3;

    // ---- fully unrolled mainloop; next-stage loads spread across kk ----
    #pragma unroll
    for (int i = 0; i < NSTAGE; i++) {
        if (i >= NSTAGE - 1) asm volatile("cp.async.wait_group 0;" ::: "memory");
        else                 asm volatile("cp.async.wait_group 1;" ::: "memory");
        __syncthreads();

        const int buf  = i % NBUF;
        const int lbuf = (i + 2) % NBUF;
        const bool doLoad = (i + 2 < NSTAGE);
        const int k0n = (i + 2) * TK;
        const uint32_t stage = smem_base + (uint32_t)(buf * STAGE_HALVES) * 2u;
        const uint32_t lst   = smem_base + (uint32_t)(lbuf * STAGE_HALVES) * 2u + stWr;
        const uint32_t aBase = stage + aOff;
        const uint32_t bBase = stage + bOff;

        #pragma unroll
        for (int kk = 0; kk < 4; kk++) {
            const uint32_t kb = (uint32_t)kk * 32u;
            uint32_t afr[2][4];
            ldsm_x4(afr[0][0], afr[0][1], afr[0][2], afr[0][3], aBase + kb);
            ldsm_x4(afr[1][0], afr[1][1], afr[1][2], afr[1][3],
                    aBase + kb + 16u * LD * 2u);
            uint32_t bfr[8][2];
            #pragma unroll
            for (int ntp = 0; ntp < 4; ntp++)
                ldsm_x4(bfr[2*ntp][0], bfr[2*ntp][1],
                        bfr[2*ntp+1][0], bfr[2*ntp+1][1],
                        bBase + kb + (uint32_t)(ntp * 16 * LD) * 2u);

            if (doLoad) {
                if (kk < 2) {
                    const int r0 = kk * 64;
                    cp16(lst + (uint32_t)(r0 * LD) * 2u,
                         Ag + (long)r0 * DIM + k0n);
                    cp16(lst + (uint32_t)((r0 + 32) * LD) * 2u,
                         Ag + (long)(r0 + 32) * DIM + k0n);
                } else {
                    const int r0 = (kk - 2) * 64;
                    cp16(lst + (uint32_t)(A_ST + r0 * LD) * 2u,
                         Bg + (long)r0 * DIM + k0n);
                    cp16(lst + (uint32_t)(A_ST + (r0 + 32) * LD) * 2u,
                         Bg + (long)(r0 + 32) * DIM + k0n);
                }
            }

            #pragma unroll
            for (int mt = 0; mt < 2; mt++)
                #pragma unroll
                for (int nt = 0; nt < 8; nt++)
                    mma_f16(acc[mt][nt], afr[mt], bfr[nt]);
        }
        if (doLoad) asm volatile("cp.async.commit_group;" ::: "memory");
    }

    // ---- epilogue (squared domain; folded constants) ----
    const float* ckArr = (mode == 0) ? g_ckn : g_ckp;
    const float* thr   = (mode == 0) ? g_dap : g_danr;
    unsigned* outAgg   = (mode == 0) ? g_hardn : g_hardp;

    const float inf = __uint_as_float(INF_BITS);

    float t2[2][2], rK[2][2], best[2][2];
    #pragma unroll
    for (int mt = 0; mt < 2; mt++)
        #pragma unroll
        for (int h = 0; h < 2; h++) {
            const int row = m0 + warpM * 32 + mt * 16 + r + h * 8;
            const float t = thr[row];
            t2[mt][h] = t * t;
            rK[mt][h] = g_rk[row];
            best[mt][h] = (mode == 0) ? 0.f : inf;
        }

    float cK[8][2];
    #pragma unroll
    for (int nt = 0; nt < 8; nt++)
        #pragma unroll
        for (int jj = 0; jj < 2; jj++)
            cK[nt][jj] = ckArr[n0 + warpN * 64 + nt * 8 + 2 * c + jj];

    if (mode == 0) {
        #pragma unroll
        for (int mt = 0; mt < 2; mt++)
            #pragma unroll
            for (int nt = 0; nt < 8; nt++)
                #pragma unroll
                for (int h = 0; h < 2; h++)
                    #pragma unroll
                    for (int jj = 0; jj < 2; jj++) {
                        float sq = fmaf(-2.f, acc[mt][nt][h * 2 + jj],
                                        rK[mt][h] + cK[nt][jj]);
                        sq = fmaxf(sq, 0.f);
                        if (sq < t2[mt][h]) best[mt][h] = fmaxf(best[mt][h], sq);
                    }
    } else {
        #pragma unroll
        for (int mt = 0; mt < 2; mt++)
            #pragma unroll
            for (int nt = 0; nt < 8; nt++)
                #pragma unroll
                for (int h = 0; h < 2; h++)
                    #pragma unroll
                    for (int jj = 0; jj < 2; jj++) {
                        float sq = fmaf(-2.f, acc[mt][nt][h * 2 + jj],
                                        rK[mt][h] + cK[nt][jj]);
                        sq = fmaxf(sq, 0.f);
                        if (sq > t2[mt][h]) best[mt][h] = fminf(best[mt][h], sq);
                    }
    }

    #pragma unroll
    for (int off = 1; off <= 2; off <<= 1)
        #pragma unroll
        for (int mt = 0; mt < 2; mt++)
            #pragma unroll
            for (int h = 0; h < 2; h++) {
                const float o = __shfl_xor_sync(0xffffffffu, best[mt][h], off);
                best[mt][h] = (mode == 0) ? fmaxf(best[mt][h], o)
                                          : fminf(best[mt][h], o);
            }

    if (tid < TM) rowRed[tid] = (mode == 0) ? 0u : INF_BITS;
    __syncthreads();

    if ((lane & 3) == 0) {
        #pragma unroll
        for (int mt = 0; mt < 2; mt++)
            #pragma unroll
            for (int h = 0; h < 2; h++) {
                const int lr = warpM * 32 + mt * 16 + r + h * 8;
                if (mode == 0) {
                    if (best[mt][h] > 0.f)
                        atomicMax(&rowRed[lr], __float_as_uint(best[mt][h]));
                } else {
                    if (best[mt][h] < inf)
                        atomicMin(&rowRed[lr], __float_as_uint(best[mt][h]));
                }
            }
    }
    __syncthreads();

    if (tid < TM) {
        const unsigned v = rowRed[tid];
        if (mode == 0) { if (v != 0u)       atomicMax(&outAgg[m0 + tid], v); }
        else           { if (v != INF_BITS) atomicMin(&outAgg[m0 + tid], v); }
    }
    __syncthreads();
    gdc_launch();
}

// ---------- finalize: 1024-thread warp-shuffle reduce + loss ----------
__global__ __launch_bounds__(1024) void finalize_kernel(float* __restrict__ out)
{
    __shared__ float w1[32], w2[32];
    __shared__ float bias_s;
    const int tid = threadIdx.x;
    const int warp = tid >> 5;

    gdc_wait();   // gemm results must be visible

    float sn = 0.f, sp = 0.f;
    for (int i = tid; i < BSZ; i += 1024) {
        sn += sqrtf(__uint_as_float(g_hardn[i]));
        const unsigned hp = g_hardp[i];
        if (hp != INF_BITS) sp += sqrtf(__uint_as_float(hp));
    }
    #pragma unroll
    for (int off = 16; off; off >>= 1) {
        sn += __shfl_down_sync(0xffffffffu, sn, off);
        sp += __shfl_down_sync(0xffffffffu, sp, off);
    }
    if ((tid & 31) == 0) { w1[warp] = sn; w2[warp] = sp; }
    __syncthreads();
    if (tid < 32) {
        float a = w1[tid], b = w2[tid];
        #pragma unroll
        for (int off = 16; off; off >>= 1) {
            a += __shfl_down_sync(0xffffffffu, a, off);
            b += __shfl_down_sync(0xffffffffu, b, off);
        }
        if (tid == 0)
            bias_s = 1.0f - 0.5f * (a / (float)BSZ) - 0.5f * (b / (float)BSZ);
    }
    __syncthreads();
    const float bias = bias_s;

    float ls = 0.f;
    for (int i = tid; i < BSZ; i += 1024)
        ls += fmaxf(g_dap[i] + bias, 0.f);
    #pragma unroll
    for (int off = 16; off; off >>= 1)
        ls += __shfl_down_sync(0xffffffffu, ls, off);
    if ((tid & 31) == 0) w1[warp] = ls;
    __syncthreads();
    if (tid < 32) {
        float a = w1[tid];
        #pragma unroll
        for (int off = 16; off; off >>= 1)
            a += __shfl_down_sync(0xffffffffu, a, off);
        if (tid == 0) out[0] = a / (float)BSZ;
    }
}

// ---------------- launch ----------------
extern "C" void kernel_launch(void* const* d_in, const int* in_sizes, int n_in,
                              void* d_out, int out_size)
{
    const float* A = (const float*)d_in[0];
    const float* P = (const float*)d_in[1];
    const float* N = (const float*)d_in[2];
    float* out = (float*)d_out;

    cudaFuncSetAttribute(gemm_mma_kernel,
                         cudaFuncAttributeMaxDynamicSharedMemorySize, SMEM_BYTES);

    rowstats_kernel<<<BSZ / 2, 256>>>(A, P, N);

    // gemm with PDL: launch setup overlaps rowstats tail
    {
        cudaLaunchConfig_t cfg = {};
        cudaLaunchAttribute attr[1];
        attr[0].id = cudaLaunchAttributeProgrammaticStreamSerialization;
        attr[0].val.programmaticStreamSerializationAllowed = 1;
        cfg.gridDim = dim3(BSZ / TN, BSZ / TM, 2);   // (32, 32, 2)
        cfg.blockDim = dim3(THREADS, 1, 1);
        cfg.dynamicSmemBytes = SMEM_BYTES;
        cfg.stream = 0;
        cfg.attrs = attr;
        cfg.numAttrs = 1;
        cudaLaunchKernelEx(&cfg, gemm_mma_kernel);
    }

    // finalize with PDL: overlaps gemm drain wave
    {
        cudaLaunchConfig_t cfg = {};
        cudaLaunchAttribute attr[1];
        attr[0].id = cudaLaunchAttributeProgrammaticStreamSerialization;
        attr[0].val.programmaticStreamSerializationAllowed = 1;
        cfg.gridDim = dim3(1, 1, 1);
        cfg.blockDim = dim3(1024, 1, 1);
        cfg.dynamicSmemBytes = 0;
        cfg.stream = 0;
        cfg.attrs = attr;
        cfg.numAttrs = 1;
        cudaLaunchKernelEx(&cfg, finalize_kernel, out);
    }
}